// round 2
// baseline (speedup 1.0000x reference)
#include <cuda_runtime.h>
#include <cuda_bf16.h>

#define NA 100000
#define NB 400000
#define NG 5000
#define SLOPEC 0.2f

// ----------------- device scratch (static; no allocations) -----------------
__device__ float         g_Z[(size_t)(NA + 64) * 512];   // [zh0|zh1|ze0|ze1] per atom
__device__ float         g_hm[(size_t)(NA + 64) * 128];  // pre-BN head-mean
__device__ float         g_U[NG * 256];                  // global_feats @ W_global
__device__ float         g_elu[NG * 2];
__device__ float         g_elh[NA * 2], g_er[NA * 2], g_eu[NA * 2];
__device__ unsigned      g_emaxkey[NA * 2];
__device__ float         g_eh[NB * 2], g_ee[NB * 2];
__device__ int           g_deg[NA], g_offs[NA], g_cursor[NA], g_blist[NB];
__device__ int           g_bsum[128], g_boff[128];
__device__ float         g_wAl[256], g_wAr[256], g_wBl[256];
__device__ __nv_bfloat16 g_Whi[512 * 128], g_Wlo[512 * 128];
__device__ float         g_bnsum[128], g_bnsumsq[128], g_bnscale[128], g_bnshift[128];

// ----------------- helpers -----------------
__device__ __forceinline__ float lrelu(float x) { return x >= 0.f ? x : SLOPEC * x; }

__device__ __forceinline__ unsigned fkey(float f) {
    unsigned u = __float_as_uint(f);
    return (u & 0x80000000u) ? ~u : (u | 0x80000000u);
}
__device__ __forceinline__ float funkey(unsigned u) {
    u = (u & 0x80000000u) ? (u & 0x7fffffffu) : ~u;
    return __uint_as_float(u);
}
__device__ __forceinline__ float dot4(float4 a, float4 b) {
    return a.x * b.x + a.y * b.y + a.z * b.z + a.w * b.w;
}
__device__ __forceinline__ float wsum(float v) {
#pragma unroll
    for (int o = 16; o > 0; o >>= 1) v += __shfl_xor_sync(0xffffffffu, v, o);
    return v;
}

// ----------------- init -----------------
__global__ void k_zero() {
    int i = blockIdx.x * blockDim.x + threadIdx.x;
    if (i < NA) g_deg[i] = 0;
    if (i < 128) { g_bnsum[i] = 0.f; g_bnsumsq[i] = 0.f; }
}

// fold attention vectors through weights: probe[h][i] = sum_d W[i, h*128+d] * attn[h*128+d]
__global__ void k_fold(const float* __restrict__ Wa, const float* __restrict__ Wb,
                       const float* __restrict__ al, const float* __restrict__ ar) {
    int m = blockIdx.x >> 1, h = blockIdx.x & 1, t = threadIdx.x;
    const float* W  = (m == 2) ? Wb : Wa;
    const float* at = (m == 1) ? ar : al;
    float s = 0.f;
    for (int d = 0; d < 128; d++) s += W[t * 256 + h * 128 + d] * at[h * 128 + d];
    float* o = (m == 0) ? g_wAl : (m == 1) ? g_wAr : g_wBl;
    o[h * 128 + t] = s;
}

// stacked weight [512,128]: rows 0-255 W_atom (h0,h1), 256-511 W_bond; x0.5 (head mean); split bf16
__global__ void k_wsplit(const float* __restrict__ Wa, const float* __restrict__ Wb) {
    int idx = blockIdx.x * 256 + threadIdx.x;   // 65536
    int k = idx >> 7, n = idx & 127;
    const float* W = (k < 256) ? Wa : Wb;
    int i = k & 127, h = (k >> 7) & 1;
    float x = 0.5f * W[i * 256 + h * 128 + n];
    __nv_bfloat16 hi = __float2bfloat16(x);
    g_Whi[idx] = hi;
    g_Wlo[idx] = __float2bfloat16(x - __bfloat162float(hi));
}

// per-global projection u = gf @ Wg  and logit el_u
__global__ void k_glob(const float* __restrict__ gf, const float* __restrict__ Wg,
                       const float* __restrict__ al) {
    __shared__ float s_gf[128];
    __shared__ float s_red[2][4];
    int g = blockIdx.x, t = threadIdx.x, lane = t & 31, wid = t >> 5;
    s_gf[t] = gf[g * 128 + t];
    __syncthreads();
    float u0 = 0.f, u1 = 0.f;
#pragma unroll 8
    for (int i = 0; i < 128; i++) {
        float x = s_gf[i];
        u0 += x * Wg[i * 256 + t];
        u1 += x * Wg[i * 256 + 128 + t];
    }
    g_U[g * 256 + t] = u0;
    g_U[g * 256 + 128 + t] = u1;
    float p0 = wsum(u0 * al[t]);
    float p1 = wsum(u1 * al[128 + t]);
    if (lane == 0) { s_red[0][wid] = p0; s_red[1][wid] = p1; }
    __syncthreads();
    if (t == 0) g_elu[2 * g]     = s_red[0][0] + s_red[0][1] + s_red[0][2] + s_red[0][3];
    if (t == 1) g_elu[2 * g + 1] = s_red[1][0] + s_red[1][1] + s_red[1][2] + s_red[1][3];
}

// per-atom logits el_h, er; g2a logit eu; emax init = eu
__global__ void k_atom(const float* __restrict__ af, const int* __restrict__ gid) {
    __shared__ float s_l[256], s_r[256];
    int t = threadIdx.x, lane = t & 31;
    if (t < 256) { s_l[t] = g_wAl[t]; s_r[t] = g_wAr[t]; }
    __syncthreads();
    int a = blockIdx.x * 8 + (t >> 5);
    float4 v = *(const float4*)&af[(size_t)a * 128 + lane * 4];
    float al0 = wsum(dot4(v, *(const float4*)&s_l[lane * 4]));
    float al1 = wsum(dot4(v, *(const float4*)&s_l[128 + lane * 4]));
    float ar0 = wsum(dot4(v, *(const float4*)&s_r[lane * 4]));
    float ar1 = wsum(dot4(v, *(const float4*)&s_r[128 + lane * 4]));
    if (lane == 0) {
        g_elh[2 * a] = al0; g_elh[2 * a + 1] = al1;
        g_er[2 * a]  = ar0; g_er[2 * a + 1]  = ar1;
        int g = gid[a];
        float eu0 = lrelu(g_elu[2 * g] + ar0);
        float eu1 = lrelu(g_elu[2 * g + 1] + ar1);
        g_eu[2 * a] = eu0; g_eu[2 * a + 1] = eu1;
        g_emaxkey[2 * a] = fkey(eu0);
        g_emaxkey[2 * a + 1] = fkey(eu1);
    }
}

// per-bond logits eh, ee; segment max; degree histogram
__global__ void k_bond(const float* __restrict__ bf, const int* __restrict__ src,
                       const int* __restrict__ dst) {
    __shared__ float s_l[256];
    int t = threadIdx.x, lane = t & 31;
    if (t < 256) s_l[t] = g_wBl[t];
    __syncthreads();
    int b = blockIdx.x * 8 + (t >> 5);
    float4 v = *(const float4*)&bf[(size_t)b * 128 + lane * 4];
    float el0 = wsum(dot4(v, *(const float4*)&s_l[lane * 4]));
    float el1 = wsum(dot4(v, *(const float4*)&s_l[128 + lane * 4]));
    if (lane == 0) {
        int s = src[b], d = dst[b];
        float er0 = g_er[2 * d], er1 = g_er[2 * d + 1];
        float eh0 = lrelu(g_elh[2 * s] + er0);
        float eh1 = lrelu(g_elh[2 * s + 1] + er1);
        float ee0 = lrelu(el0 + er0);
        float ee1 = lrelu(el1 + er1);
        g_eh[2 * b] = eh0; g_eh[2 * b + 1] = eh1;
        g_ee[2 * b] = ee0; g_ee[2 * b + 1] = ee1;
        atomicMax(&g_emaxkey[2 * d],     fkey(fmaxf(eh0, ee0)));
        atomicMax(&g_emaxkey[2 * d + 1], fkey(fmaxf(eh1, ee1)));
        atomicAdd(&g_deg[d], 1);
    }
}

// ---- 2-level exclusive scan of degrees -> CSR offsets ----
__global__ void k_scan1() {
    __shared__ int s[1024];
    int t = threadIdx.x, idx = blockIdx.x * 1024 + t;
    s[t] = (idx < NA) ? g_deg[idx] : 0;
    __syncthreads();
    for (int o = 512; o > 0; o >>= 1) {
        if (t < o) s[t] += s[t + o];
        __syncthreads();
    }
    if (t == 0) g_bsum[blockIdx.x] = s[0];
}
__global__ void k_scan2(int nblk) {
    if (threadIdx.x == 0) {
        int run = 0;
        for (int i = 0; i < nblk; i++) { int v = g_bsum[i]; g_boff[i] = run; run += v; }
    }
}
__global__ void k_scan3() {
    __shared__ int s[1024];
    int t = threadIdx.x, idx = blockIdx.x * 1024 + t;
    int v = (idx < NA) ? g_deg[idx] : 0;
    s[t] = v;
    __syncthreads();
    for (int o = 1; o < 1024; o <<= 1) {
        int add = (t >= o) ? s[t - o] : 0;
        __syncthreads();
        s[t] += add;
        __syncthreads();
    }
    int excl = s[t] - v + g_boff[blockIdx.x];
    if (idx < NA) { g_offs[idx] = excl; g_cursor[idx] = excl; }
}
__global__ void k_scatter(const int* __restrict__ dst) {
    int b = blockIdx.x * blockDim.x + threadIdx.x;
    if (b >= NB) return;
    int pos = atomicAdd(&g_cursor[dst[b]], 1);
    g_blist[pos] = b;
}

// ---- gather: softmax-weighted raw-feature aggregation; writes Z and hm base ----
__global__ void k_gather(const float* __restrict__ af, const float* __restrict__ bf,
                         const int* __restrict__ src, const int* __restrict__ gid) {
    int lane = threadIdx.x & 31;
    int a = blockIdx.x * 8 + (threadIdx.x >> 5);
    float emax0 = funkey(g_emaxkey[2 * a]);
    float emax1 = funkey(g_emaxkey[2 * a + 1]);
    float aH0x = 0, aH0y = 0, aH0z = 0, aH0w = 0, aH1x = 0, aH1y = 0, aH1z = 0, aH1w = 0;
    float aE0x = 0, aE0y = 0, aE0z = 0, aE0w = 0, aE1x = 0, aE1y = 0, aE1z = 0, aE1w = 0;
    float s0 = 0.f, s1 = 0.f;
    int beg = g_offs[a], end = beg + g_deg[a];
    for (int i = beg; i < end; i++) {
        int b = g_blist[i];
        float xh0 = __expf(g_eh[2 * b] - emax0);
        float xh1 = __expf(g_eh[2 * b + 1] - emax1);
        float xe0 = __expf(g_ee[2 * b] - emax0);
        float xe1 = __expf(g_ee[2 * b + 1] - emax1);
        s0 += xh0 + xe0;
        s1 += xh1 + xe1;
        int sidx = src[b];
        float4 av = *(const float4*)&af[(size_t)sidx * 128 + lane * 4];
        float4 bv = *(const float4*)&bf[(size_t)b * 128 + lane * 4];
        aH0x += xh0 * av.x; aH0y += xh0 * av.y; aH0z += xh0 * av.z; aH0w += xh0 * av.w;
        aH1x += xh1 * av.x; aH1y += xh1 * av.y; aH1z += xh1 * av.z; aH1w += xh1 * av.w;
        aE0x += xe0 * bv.x; aE0y += xe0 * bv.y; aE0z += xe0 * bv.z; aE0w += xe0 * bv.w;
        aE1x += xe1 * bv.x; aE1y += xe1 * bv.y; aE1z += xe1 * bv.z; aE1w += xe1 * bv.w;
    }
    float xu0 = __expf(g_eu[2 * a] - emax0);
    float xu1 = __expf(g_eu[2 * a + 1] - emax1);
    float inv0 = 1.f / (s0 + xu0);
    float inv1 = 1.f / (s1 + xu1);
    float* zp = &g_Z[(size_t)a * 512 + lane * 4];
    *(float4*)(zp)       = make_float4(aH0x * inv0, aH0y * inv0, aH0z * inv0, aH0w * inv0);
    *(float4*)(zp + 128) = make_float4(aH1x * inv1, aH1y * inv1, aH1z * inv1, aH1w * inv1);
    *(float4*)(zp + 256) = make_float4(aE0x * inv0, aE0y * inv0, aE0z * inv0, aE0w * inv0);
    *(float4*)(zp + 384) = make_float4(aE1x * inv1, aE1y * inv1, aE1z * inv1, aE1w * inv1);
    int g = gid[a];
    float4 u0 = *(const float4*)&g_U[g * 256 + lane * 4];
    float4 u1 = *(const float4*)&g_U[g * 256 + 128 + lane * 4];
    float au0 = 0.5f * xu0 * inv0, au1 = 0.5f * xu1 * inv1;
    float4 hb = make_float4(u0.x * au0 + u1.x * au1, u0.y * au0 + u1.y * au1,
                            u0.z * au0 + u1.z * au1, u0.w * au0 + u1.w * au1);
    *(float4*)&g_hm[(size_t)a * 128 + lane * 4] = hb;
}

// ---- split-bf16 tensor-core GEMM: hm += Z[100k,512] @ Wstack[512,128] ----
#define MMA_OP(c, A0, A1, A2, A3, B0, B1)                                              \
    asm volatile("mma.sync.aligned.m16n8k16.row.col.f32.bf16.bf16.f32 "                \
                 "{%0,%1,%2,%3}, {%4,%5,%6,%7}, {%8,%9}, {%0,%1,%2,%3};"               \
                 : "+f"(c[0]), "+f"(c[1]), "+f"(c[2]), "+f"(c[3])                      \
                 : "r"(A0), "r"(A1), "r"(A2), "r"(A3), "r"(B0), "r"(B1))

__global__ __launch_bounds__(256) void k_gemm() {
    __shared__ __align__(16) __nv_bfloat16 sAh[64 * 34], sAl[64 * 34];
    __shared__ __align__(16) __nv_bfloat16 sBh[128 * 34], sBl[128 * 34];
    int tid = threadIdx.x;
    int row0 = blockIdx.x * 64;
    int wid = tid >> 5, lane = tid & 31;
    int wm = wid & 3, wn = wid >> 2;
    int g = lane >> 2, t = lane & 3;
    float acc[8][4];
#pragma unroll
    for (int i = 0; i < 8; i++)
#pragma unroll
        for (int j = 0; j < 4; j++) acc[i][j] = 0.f;

    for (int k0 = 0; k0 < 512; k0 += 32) {
        __syncthreads();
        {   // stage A (fp32 -> hi/lo bf16)
            int r = tid >> 2, kk = (tid & 3) * 8;
            const float* p = &g_Z[(size_t)(row0 + r) * 512 + k0 + kk];
            float4 f0 = *(const float4*)p;
            float4 f1 = *(const float4*)(p + 4);
            float vv[8] = {f0.x, f0.y, f0.z, f0.w, f1.x, f1.y, f1.z, f1.w};
#pragma unroll
            for (int j = 0; j < 8; j++) {
                __nv_bfloat16 hi = __float2bfloat16(vv[j]);
                sAh[r * 34 + kk + j] = hi;
                sAl[r * 34 + kk + j] = __float2bfloat16(vv[j] - __bfloat162float(hi));
            }
        }
#pragma unroll
        for (int i = 0; i < 16; i++) {   // stage B transposed [n][k]
            int e = tid + i * 256;
            int kk = e >> 7, n = e & 127;
            sBh[n * 34 + kk] = g_Whi[(k0 + kk) * 128 + n];
            sBl[n * 34 + kk] = g_Wlo[(k0 + kk) * 128 + n];
        }
        __syncthreads();
#pragma unroll
        for (int s = 0; s < 2; s++) {
            int m0 = wm * 16;
            int ka = s * 16 + 2 * t;
            unsigned ah0 = *(const unsigned*)&sAh[(m0 + g) * 34 + ka];
            unsigned ah1 = *(const unsigned*)&sAh[(m0 + g + 8) * 34 + ka];
            unsigned ah2 = *(const unsigned*)&sAh[(m0 + g) * 34 + ka + 8];
            unsigned ah3 = *(const unsigned*)&sAh[(m0 + g + 8) * 34 + ka + 8];
            unsigned al0 = *(const unsigned*)&sAl[(m0 + g) * 34 + ka];
            unsigned al1 = *(const unsigned*)&sAl[(m0 + g + 8) * 34 + ka];
            unsigned al2 = *(const unsigned*)&sAl[(m0 + g) * 34 + ka + 8];
            unsigned al3 = *(const unsigned*)&sAl[(m0 + g + 8) * 34 + ka + 8];
#pragma unroll
            for (int nt = 0; nt < 8; nt++) {
                int n = wn * 64 + nt * 8 + g;
                unsigned bh0 = *(const unsigned*)&sBh[n * 34 + ka];
                unsigned bh1 = *(const unsigned*)&sBh[n * 34 + ka + 8];
                unsigned bl0 = *(const unsigned*)&sBl[n * 34 + ka];
                unsigned bl1 = *(const unsigned*)&sBl[n * 34 + ka + 8];
                MMA_OP(acc[nt], ah0, ah1, ah2, ah3, bh0, bh1);
                MMA_OP(acc[nt], al0, al1, al2, al3, bh0, bh1);
                MMA_OP(acc[nt], ah0, ah1, ah2, ah3, bl0, bl1);
            }
        }
    }
#pragma unroll
    for (int nt = 0; nt < 8; nt++) {
        int col = wn * 64 + nt * 8 + 2 * t;
        int r0 = row0 + wm * 16 + g;
        if (r0 < NA) {
            float2 b = *(float2*)&g_hm[(size_t)r0 * 128 + col];
            b.x += acc[nt][0]; b.y += acc[nt][1];
            *(float2*)&g_hm[(size_t)r0 * 128 + col] = b;
        }
        int r1 = r0 + 8;
        if (r1 < NA) {
            float2 b = *(float2*)&g_hm[(size_t)r1 * 128 + col];
            b.x += acc[nt][2]; b.y += acc[nt][3];
            *(float2*)&g_hm[(size_t)r1 * 128 + col] = b;
        }
    }
}

// ---- batchnorm (batch stats) + relu ----
__global__ void k_bnstats() {
    int t = threadIdx.x;   // 128 = column
    int r0 = blockIdx.x * 512;
    float s = 0.f, ss = 0.f;
    for (int j = 0; j < 512; j++) {
        int r = r0 + j;
        if (r >= NA) break;
        float v = g_hm[(size_t)r * 128 + t];
        s += v; ss += v * v;
    }
    atomicAdd(&g_bnsum[t], s);
    atomicAdd(&g_bnsumsq[t], ss);
}
__global__ void k_bnfinal(const float* __restrict__ gamma, const float* __restrict__ beta) {
    int t = threadIdx.x;
    float m = g_bnsum[t] / (float)NA;
    float var = g_bnsumsq[t] / (float)NA - m * m;
    float sc = gamma[t] / sqrtf(var + 1e-5f);
    g_bnscale[t] = sc;
    g_bnshift[t] = beta[t] - m * sc;
}
__global__ void k_bnapply(float* __restrict__ out) {
    int i = blockIdx.x * blockDim.x + threadIdx.x;
    if (i >= NA * 128) return;
    int c = i & 127;
    out[i] = fmaxf(g_hm[i] * g_bnscale[c] + g_bnshift[c], 0.f);
}

// ----------------- launch -----------------
extern "C" void kernel_launch(void* const* d_in, const int* in_sizes, int n_in,
                              void* d_out, int out_size) {
    const float* atom_feats   = (const float*)d_in[0];
    const float* bond_feats   = (const float*)d_in[1];
    const float* global_feats = (const float*)d_in[2];
    const float* W_atom       = (const float*)d_in[3];
    const float* W_bond       = (const float*)d_in[4];
    const float* W_global     = (const float*)d_in[5];
    const float* attn_l       = (const float*)d_in[6];
    const float* attn_r       = (const float*)d_in[7];
    const float* bn_gamma     = (const float*)d_in[8];
    const float* bn_beta      = (const float*)d_in[9];
    const int*   src          = (const int*)d_in[10];
    const int*   dst          = (const int*)d_in[11];
    const int*   gid          = (const int*)d_in[12];
    float* out = (float*)d_out;

    const int nscan = (NA + 1023) / 1024;   // 98

    k_zero<<<(NA + 1023) / 1024, 1024>>>();
    k_fold<<<6, 128>>>(W_atom, W_bond, attn_l, attn_r);
    k_wsplit<<<256, 256>>>(W_atom, W_bond);
    k_glob<<<NG, 128>>>(global_feats, W_global, attn_l);
    k_atom<<<NA / 8, 256>>>(atom_feats, gid);
    k_bond<<<NB / 8, 256>>>(bond_feats, src, dst);
    k_scan1<<<nscan, 1024>>>();
    k_scan2<<<1, 32>>>(nscan);
    k_scan3<<<nscan, 1024>>>();
    k_scatter<<<(NB + 255) / 256, 256>>>(dst);
    k_gather<<<NA / 8, 256>>>(atom_feats, bond_feats, src, gid);
    k_gemm<<<(NA + 63) / 64, 256>>>();
    k_bnstats<<<(NA + 511) / 512, 128>>>();
    k_bnfinal<<<1, 128>>>(bn_gamma, bn_beta);
    k_bnapply<<<(NA * 128 + 1023) / 1024, 1024>>>(out);
}

// round 3
// speedup vs baseline: 1.2261x; 1.2261x over previous
#include <cuda_runtime.h>
#include <cuda_bf16.h>

#define NA 100000
#define NB 400000
#define NG 5000
#define SLOPEC 0.2f

// ----------------- device scratch (static; no allocations) -----------------
__device__ __align__(256) __nv_bfloat16 g_Zhi[(size_t)(NA + 64) * 512];
__device__ __align__(256) __nv_bfloat16 g_Zlo[(size_t)(NA + 64) * 512];
__device__ __align__(256) float         g_hm[(size_t)(NA + 64) * 128];
__device__ __align__(256) float         g_U[NG * 256];
__device__ float         g_elu[NG * 2];
__device__ float         g_elh[NA * 2], g_er[NA * 2], g_eu[NA * 2];
__device__ unsigned      g_emaxkey[NA * 2];
__device__ __align__(16) float g_ehee[NB * 4];         // (eh0, eh1, ee0, ee1)
__device__ int           g_deg[NA], g_cursor[NA], g_blist[NB];
__device__ int2          g_range[NA];                  // (beg, end)
__device__ int           g_bsum[128], g_boff[128];
__device__ float         g_wAl[256], g_wAr[256], g_wBl[256];
__device__ __align__(256) __nv_bfloat16 g_WhiT[128 * 512];  // [n][k] transposed, x0.5 folded
__device__ __align__(256) __nv_bfloat16 g_WloT[128 * 512];
__device__ float         g_bnsum[128], g_bnsumsq[128], g_bnscale[128], g_bnshift[128];

// ----------------- helpers -----------------
__device__ __forceinline__ float lrelu(float x) { return x >= 0.f ? x : SLOPEC * x; }

__device__ __forceinline__ unsigned fkey(float f) {
    unsigned u = __float_as_uint(f);
    return (u & 0x80000000u) ? ~u : (u | 0x80000000u);
}
__device__ __forceinline__ float funkey(unsigned u) {
    u = (u & 0x80000000u) ? (u & 0x7fffffffu) : ~u;
    return __uint_as_float(u);
}
__device__ __forceinline__ float dot4(float4 a, float4 b) {
    return a.x * b.x + a.y * b.y + a.z * b.z + a.w * b.w;
}
__device__ __forceinline__ float wsum(float v) {
#pragma unroll
    for (int o = 16; o > 0; o >>= 1) v += __shfl_xor_sync(0xffffffffu, v, o);
    return v;
}

// split fp32 float4 -> bf16 hi plane + lo plane (4 elems, 8B each)
__device__ __forceinline__ void split_store(__nv_bfloat16* ph, __nv_bfloat16* pl, float4 v) {
    __nv_bfloat162 h0 = __floats2bfloat162_rn(v.x, v.y);
    __nv_bfloat162 h1 = __floats2bfloat162_rn(v.z, v.w);
    __nv_bfloat162 l0 = __floats2bfloat162_rn(v.x - __bfloat162float(h0.x),
                                              v.y - __bfloat162float(h0.y));
    __nv_bfloat162 l1 = __floats2bfloat162_rn(v.z - __bfloat162float(h1.x),
                                              v.w - __bfloat162float(h1.y));
    *(__nv_bfloat162*)(ph)     = h0;
    *(__nv_bfloat162*)(ph + 2) = h1;
    *(__nv_bfloat162*)(pl)     = l0;
    *(__nv_bfloat162*)(pl + 2) = l1;
}

// ----------------- merged prep: zero + fold probes + split/transpose weights ------
__global__ void k_prep(const float* __restrict__ Wa, const float* __restrict__ Wb,
                       const float* __restrict__ al, const float* __restrict__ ar) {
    int b = blockIdx.x, t = threadIdx.x;
    if (b < 391) {                       // zero degree + bn accumulators
        int i = b * 256 + t;
        if (i < NA) g_deg[i] = 0;
        if (b == 0 && t < 128) { g_bnsum[t] = 0.f; g_bnsumsq[t] = 0.f; }
    } else if (b < 397) {                // fold attention probes through weights
        if (t < 128) {
            int m = (b - 391) >> 1, h = (b - 391) & 1;
            const float* W  = (m == 2) ? Wb : Wa;
            const float* at = (m == 1) ? ar : al;
            float s = 0.f;
            for (int d = 0; d < 128; d++) s += W[t * 256 + h * 128 + d] * at[h * 128 + d];
            float* o = (m == 0) ? g_wAl : (m == 1) ? g_wAr : g_wBl;
            o[h * 128 + t] = s;
        }
    } else {                             // split + transpose stacked weight, x0.5 (head mean)
        int idx = (b - 397) * 256 + t;   // 65536 = n*512 + k
        int n = idx >> 9, k = idx & 511;
        int s2 = k >> 7, i = k & 127, h = s2 & 1;
        const float* W = (s2 < 2) ? Wa : Wb;
        float x = 0.5f * W[i * 256 + h * 128 + n];
        __nv_bfloat16 hi = __float2bfloat16(x);
        g_WhiT[idx] = hi;
        g_WloT[idx] = __float2bfloat16(x - __bfloat162float(hi));
    }
}

// ----------------- per-global projection + logit; 16 globals per block ----------
__global__ __launch_bounds__(256) void k_glob(const float* __restrict__ gf,
                                              const float* __restrict__ Wg,
                                              const float* __restrict__ al) {
    __shared__ float s_gf[16][128];
    __shared__ float s_elu[32];
    int g0 = blockIdx.x * 16, t = threadIdx.x, lane = t & 31;
    int head = t >> 7;
    if (t < 32) s_elu[t] = 0.f;
#pragma unroll
    for (int p = 0; p < 8; p++) {        // 2048 elems / 256 threads
        int e = t + p * 256;
        int j = e >> 7, d = e & 127;
        s_gf[j][d] = (g0 + j < NG) ? gf[(g0 + j) * 128 + d] : 0.f;
    }
    __syncthreads();
    float acc[16];
#pragma unroll
    for (int j = 0; j < 16; j++) acc[j] = 0.f;
    for (int i = 0; i < 128; i++) {
        float w = Wg[i * 256 + t];
#pragma unroll
        for (int j = 0; j < 16; j++) acc[j] += s_gf[j][i] * w;
    }
    float alt = al[t];
#pragma unroll
    for (int j = 0; j < 16; j++) {
        if (g0 + j < NG) g_U[(g0 + j) * 256 + t] = acc[j];
        float p = wsum(acc[j] * alt);
        if (lane == 0) atomicAdd(&s_elu[j * 2 + head], p);
    }
    __syncthreads();
    if (t < 32) {
        int j = t >> 1, h = t & 1;
        if (g0 + j < NG) g_elu[(g0 + j) * 2 + h] = s_elu[j * 2 + h];
    }
}

// ----------------- per-atom logits -----------------
__global__ void k_atom(const float* __restrict__ af, const int* __restrict__ gid) {
    __shared__ float s_l[256], s_r[256];
    int t = threadIdx.x, lane = t & 31;
    if (t < 256) { s_l[t] = g_wAl[t]; s_r[t] = g_wAr[t]; }
    __syncthreads();
    int a = blockIdx.x * 8 + (t >> 5);
    float4 v = *(const float4*)&af[(size_t)a * 128 + lane * 4];
    float al0 = wsum(dot4(v, *(const float4*)&s_l[lane * 4]));
    float al1 = wsum(dot4(v, *(const float4*)&s_l[128 + lane * 4]));
    float ar0 = wsum(dot4(v, *(const float4*)&s_r[lane * 4]));
    float ar1 = wsum(dot4(v, *(const float4*)&s_r[128 + lane * 4]));
    if (lane == 0) {
        g_elh[2 * a] = al0; g_elh[2 * a + 1] = al1;
        g_er[2 * a]  = ar0; g_er[2 * a + 1]  = ar1;
        int g = gid[a];
        float eu0 = lrelu(g_elu[2 * g] + ar0);
        float eu1 = lrelu(g_elu[2 * g + 1] + ar1);
        g_eu[2 * a] = eu0; g_eu[2 * a + 1] = eu1;
        g_emaxkey[2 * a] = fkey(eu0);
        g_emaxkey[2 * a + 1] = fkey(eu1);
    }
}

// ----------------- per-bond logits + segment max + degree histogram --------------
__global__ void k_bond(const float* __restrict__ bf, const int* __restrict__ src,
                       const int* __restrict__ dst) {
    __shared__ float s_l[256];
    int t = threadIdx.x, lane = t & 31;
    if (t < 256) s_l[t] = g_wBl[t];
    __syncthreads();
    int b = blockIdx.x * 8 + (t >> 5);
    float4 v = *(const float4*)&bf[(size_t)b * 128 + lane * 4];
    float el0 = wsum(dot4(v, *(const float4*)&s_l[lane * 4]));
    float el1 = wsum(dot4(v, *(const float4*)&s_l[128 + lane * 4]));
    if (lane == 0) {
        int s = src[b], d = dst[b];
        float er0 = g_er[2 * d], er1 = g_er[2 * d + 1];
        float eh0 = lrelu(g_elh[2 * s] + er0);
        float eh1 = lrelu(g_elh[2 * s + 1] + er1);
        float ee0 = lrelu(el0 + er0);
        float ee1 = lrelu(el1 + er1);
        *(float4*)&g_ehee[4 * b] = make_float4(eh0, eh1, ee0, ee1);
        atomicMax(&g_emaxkey[2 * d],     fkey(fmaxf(eh0, ee0)));
        atomicMax(&g_emaxkey[2 * d + 1], fkey(fmaxf(eh1, ee1)));
        atomicAdd(&g_deg[d], 1);
    }
}

// ---- 2-level exclusive scan of degrees -> CSR ranges ----
__global__ void k_scan1() {
    __shared__ int s[1024];
    int t = threadIdx.x, idx = blockIdx.x * 1024 + t;
    s[t] = (idx < NA) ? g_deg[idx] : 0;
    __syncthreads();
    for (int o = 512; o > 0; o >>= 1) {
        if (t < o) s[t] += s[t + o];
        __syncthreads();
    }
    if (t == 0) g_bsum[blockIdx.x] = s[0];
}
__global__ void k_scan2(int nblk) {
    if (threadIdx.x == 0) {
        int run = 0;
        for (int i = 0; i < nblk; i++) { int v = g_bsum[i]; g_boff[i] = run; run += v; }
    }
}
__global__ void k_scan3() {
    __shared__ int s[1024];
    int t = threadIdx.x, idx = blockIdx.x * 1024 + t;
    int v = (idx < NA) ? g_deg[idx] : 0;
    s[t] = v;
    __syncthreads();
    for (int o = 1; o < 1024; o <<= 1) {
        int add = (t >= o) ? s[t - o] : 0;
        __syncthreads();
        s[t] += add;
        __syncthreads();
    }
    int excl = s[t] - v + g_boff[blockIdx.x];
    if (idx < NA) { g_range[idx] = make_int2(excl, excl + v); g_cursor[idx] = excl; }
}
__global__ void k_scatter(const int* __restrict__ dst) {
    int b = blockIdx.x * blockDim.x + threadIdx.x;
    if (b >= NB) return;
    int pos = atomicAdd(&g_cursor[dst[b]], 1);
    g_blist[pos] = b;
}

// ---- gather: softmax-weighted raw-feature aggregation, 4-way pipelined ----
__global__ __launch_bounds__(256) void k_gather(const float* __restrict__ af,
                                                const float* __restrict__ bf,
                                                const int* __restrict__ src,
                                                const int* __restrict__ gid) {
    int lane = threadIdx.x & 31;
    int a = blockIdx.x * 8 + (threadIdx.x >> 5);
    uint2 mk = *(const uint2*)&g_emaxkey[2 * a];
    float emax0 = funkey(mk.x), emax1 = funkey(mk.y);
    int2 rg = g_range[a];
    float4 aH0 = make_float4(0, 0, 0, 0), aH1 = aH0, aE0 = aH0, aE1 = aH0;
    float s0 = 0.f, s1 = 0.f;
    int i = rg.x, end = rg.y;
    for (; i + 4 <= end; i += 4) {
        int bs[4], ss[4];
        float4 ev[4], avs[4], bvs[4];
#pragma unroll
        for (int j = 0; j < 4; j++) bs[j] = g_blist[i + j];
#pragma unroll
        for (int j = 0; j < 4; j++) ss[j] = src[bs[j]];
#pragma unroll
        for (int j = 0; j < 4; j++) ev[j] = *(const float4*)&g_ehee[4 * bs[j]];
#pragma unroll
        for (int j = 0; j < 4; j++) {
            avs[j] = *(const float4*)&af[(size_t)ss[j] * 128 + lane * 4];
            bvs[j] = *(const float4*)&bf[(size_t)bs[j] * 128 + lane * 4];
        }
#pragma unroll
        for (int j = 0; j < 4; j++) {
            float xh0 = __expf(ev[j].x - emax0), xh1 = __expf(ev[j].y - emax1);
            float xe0 = __expf(ev[j].z - emax0), xe1 = __expf(ev[j].w - emax1);
            s0 += xh0 + xe0; s1 += xh1 + xe1;
            aH0.x += xh0 * avs[j].x; aH0.y += xh0 * avs[j].y;
            aH0.z += xh0 * avs[j].z; aH0.w += xh0 * avs[j].w;
            aH1.x += xh1 * avs[j].x; aH1.y += xh1 * avs[j].y;
            aH1.z += xh1 * avs[j].z; aH1.w += xh1 * avs[j].w;
            aE0.x += xe0 * bvs[j].x; aE0.y += xe0 * bvs[j].y;
            aE0.z += xe0 * bvs[j].z; aE0.w += xe0 * bvs[j].w;
            aE1.x += xe1 * bvs[j].x; aE1.y += xe1 * bvs[j].y;
            aE1.z += xe1 * bvs[j].z; aE1.w += xe1 * bvs[j].w;
        }
    }
    for (; i < end; i++) {
        int b = g_blist[i];
        int s = src[b];
        float4 ev = *(const float4*)&g_ehee[4 * b];
        float4 av = *(const float4*)&af[(size_t)s * 128 + lane * 4];
        float4 bv = *(const float4*)&bf[(size_t)b * 128 + lane * 4];
        float xh0 = __expf(ev.x - emax0), xh1 = __expf(ev.y - emax1);
        float xe0 = __expf(ev.z - emax0), xe1 = __expf(ev.w - emax1);
        s0 += xh0 + xe0; s1 += xh1 + xe1;
        aH0.x += xh0 * av.x; aH0.y += xh0 * av.y; aH0.z += xh0 * av.z; aH0.w += xh0 * av.w;
        aH1.x += xh1 * av.x; aH1.y += xh1 * av.y; aH1.z += xh1 * av.z; aH1.w += xh1 * av.w;
        aE0.x += xe0 * bv.x; aE0.y += xe0 * bv.y; aE0.z += xe0 * bv.z; aE0.w += xe0 * bv.w;
        aE1.x += xe1 * bv.x; aE1.y += xe1 * bv.y; aE1.z += xe1 * bv.z; aE1.w += xe1 * bv.w;
    }
    float xu0 = __expf(g_eu[2 * a] - emax0);
    float xu1 = __expf(g_eu[2 * a + 1] - emax1);
    float inv0 = 1.f / (s0 + xu0);
    float inv1 = 1.f / (s1 + xu1);
    size_t zb = (size_t)a * 512 + lane * 4;
    split_store(&g_Zhi[zb], &g_Zlo[zb],
                make_float4(aH0.x * inv0, aH0.y * inv0, aH0.z * inv0, aH0.w * inv0));
    split_store(&g_Zhi[zb + 128], &g_Zlo[zb + 128],
                make_float4(aH1.x * inv1, aH1.y * inv1, aH1.z * inv1, aH1.w * inv1));
    split_store(&g_Zhi[zb + 256], &g_Zlo[zb + 256],
                make_float4(aE0.x * inv0, aE0.y * inv0, aE0.z * inv0, aE0.w * inv0));
    split_store(&g_Zhi[zb + 384], &g_Zlo[zb + 384],
                make_float4(aE1.x * inv1, aE1.y * inv1, aE1.z * inv1, aE1.w * inv1));
    int g = gid[a];
    float4 u0 = *(const float4*)&g_U[g * 256 + lane * 4];
    float4 u1 = *(const float4*)&g_U[g * 256 + 128 + lane * 4];
    float au0 = 0.5f * xu0 * inv0, au1 = 0.5f * xu1 * inv1;
    float4 hb = make_float4(u0.x * au0 + u1.x * au1, u0.y * au0 + u1.y * au1,
                            u0.z * au0 + u1.z * au1, u0.w * au0 + u1.w * au1);
    *(float4*)&g_hm[(size_t)a * 128 + lane * 4] = hb;
}

// ---- split-bf16 tensor-core GEMM with cp.async double buffering ----
// smem per stage: Ah 9216B | Al 9216B | Bh 18432B | Bl 18432B = 55296B; 2 stages.
#define STG_BYTES 55296
#define CP16(saddr, gptr) \
    asm volatile("cp.async.cg.shared.global [%0], [%1], 16;\n" :: "r"(saddr), "l"(gptr))

__device__ __forceinline__ void gemm_load_stage(unsigned char* dsm, int st, int row0,
                                                int k0, int tid) {
    unsigned sa = (unsigned)__cvta_generic_to_shared(dsm + st * STG_BYTES);
#pragma unroll
    for (int p = 0; p < 2; p++) {          // A: 64 rows x 64 k bf16, 8 segs of 16B
        int e = tid + p * 256;
        int r = e >> 3, seg = e & 7;
        size_t go = (size_t)(row0 + r) * 512 + k0 + seg * 8;
        unsigned so = (unsigned)(r * 72 + seg * 8) * 2;
        CP16(sa + so, &g_Zhi[go]);
        CP16(sa + 9216 + so, &g_Zlo[go]);
    }
#pragma unroll
    for (int p = 0; p < 4; p++) {          // B: 128 n-rows x 64 k
        int e = tid + p * 256;
        int n = e >> 3, seg = e & 7;
        size_t go = (size_t)n * 512 + k0 + seg * 8;
        unsigned so = (unsigned)(n * 72 + seg * 8) * 2;
        CP16(sa + 18432 + so, &g_WhiT[go]);
        CP16(sa + 36864 + so, &g_WloT[go]);
    }
    asm volatile("cp.async.commit_group;\n" ::);
}

#define MMA_OP(c, A0, A1, A2, A3, B0, B1)                                              \
    asm volatile("mma.sync.aligned.m16n8k16.row.col.f32.bf16.bf16.f32 "                \
                 "{%0,%1,%2,%3}, {%4,%5,%6,%7}, {%8,%9}, {%0,%1,%2,%3};"               \
                 : "+f"(c[0]), "+f"(c[1]), "+f"(c[2]), "+f"(c[3])                      \
                 : "r"(A0), "r"(A1), "r"(A2), "r"(A3), "r"(B0), "r"(B1))

__global__ __launch_bounds__(256) void k_gemm() {
    extern __shared__ __align__(16) unsigned char dsm[];
    int tid = threadIdx.x;
    int row0 = blockIdx.x * 64;
    int wid = tid >> 5, lane = tid & 31;
    int wm = wid & 3, wn = wid >> 2;
    int g = lane >> 2, t = lane & 3;
    float acc[8][4];
#pragma unroll
    for (int i = 0; i < 8; i++)
#pragma unroll
        for (int j = 0; j < 4; j++) acc[i][j] = 0.f;

    gemm_load_stage(dsm, 0, row0, 0, tid);
#pragma unroll 1
    for (int c = 0; c < 8; c++) {
        if (c < 7) {
            gemm_load_stage(dsm, (c + 1) & 1, row0, (c + 1) * 64, tid);
            asm volatile("cp.async.wait_group 1;\n" ::);
        } else {
            asm volatile("cp.async.wait_group 0;\n" ::);
        }
        __syncthreads();
        const __nv_bfloat16* sAh = (const __nv_bfloat16*)(dsm + (c & 1) * STG_BYTES);
        const __nv_bfloat16* sAl = sAh + 4608;
        const __nv_bfloat16* sBh = sAh + 9216;
        const __nv_bfloat16* sBl = sAh + 18432;
        int m0 = wm * 16;
#pragma unroll
        for (int s = 0; s < 4; s++) {
            int ka = s * 16 + 2 * t;
            unsigned ah0 = *(const unsigned*)&sAh[(m0 + g) * 72 + ka];
            unsigned ah1 = *(const unsigned*)&sAh[(m0 + g + 8) * 72 + ka];
            unsigned ah2 = *(const unsigned*)&sAh[(m0 + g) * 72 + ka + 8];
            unsigned ah3 = *(const unsigned*)&sAh[(m0 + g + 8) * 72 + ka + 8];
            unsigned al0 = *(const unsigned*)&sAl[(m0 + g) * 72 + ka];
            unsigned al1 = *(const unsigned*)&sAl[(m0 + g + 8) * 72 + ka];
            unsigned al2 = *(const unsigned*)&sAl[(m0 + g) * 72 + ka + 8];
            unsigned al3 = *(const unsigned*)&sAl[(m0 + g + 8) * 72 + ka + 8];
#pragma unroll
            for (int nt = 0; nt < 8; nt++) {
                int n = wn * 64 + nt * 8 + g;
                unsigned bh0 = *(const unsigned*)&sBh[n * 72 + ka];
                unsigned bh1 = *(const unsigned*)&sBh[n * 72 + ka + 8];
                unsigned bl0 = *(const unsigned*)&sBl[n * 72 + ka];
                unsigned bl1 = *(const unsigned*)&sBl[n * 72 + ka + 8];
                MMA_OP(acc[nt], ah0, ah1, ah2, ah3, bh0, bh1);
                MMA_OP(acc[nt], al0, al1, al2, al3, bh0, bh1);
                MMA_OP(acc[nt], ah0, ah1, ah2, ah3, bl0, bl1);
            }
        }
        __syncthreads();
    }
#pragma unroll
    for (int nt = 0; nt < 8; nt++) {
        int col = wn * 64 + nt * 8 + 2 * t;
        int r0 = row0 + wm * 16 + g;
        if (r0 < NA) {
            float2 b = *(float2*)&g_hm[(size_t)r0 * 128 + col];
            b.x += acc[nt][0]; b.y += acc[nt][1];
            *(float2*)&g_hm[(size_t)r0 * 128 + col] = b;
        }
        int r1 = r0 + 8;
        if (r1 < NA) {
            float2 b = *(float2*)&g_hm[(size_t)r1 * 128 + col];
            b.x += acc[nt][2]; b.y += acc[nt][3];
            *(float2*)&g_hm[(size_t)r1 * 128 + col] = b;
        }
    }
}

// ---- batchnorm (batch stats) + relu ----
__global__ void k_bnstats() {
    int t = threadIdx.x;
    int r0 = blockIdx.x * 512;
    float s = 0.f, ss = 0.f;
    for (int j = 0; j < 512; j++) {
        int r = r0 + j;
        if (r >= NA) break;
        float v = g_hm[(size_t)r * 128 + t];
        s += v; ss += v * v;
    }
    atomicAdd(&g_bnsum[t], s);
    atomicAdd(&g_bnsumsq[t], ss);
}
__global__ void k_bnfinal(const float* __restrict__ gamma, const float* __restrict__ beta) {
    int t = threadIdx.x;
    float m = g_bnsum[t] / (float)NA;
    float var = g_bnsumsq[t] / (float)NA - m * m;
    float sc = gamma[t] / sqrtf(var + 1e-5f);
    g_bnscale[t] = sc;
    g_bnshift[t] = beta[t] - m * sc;
}
__global__ void k_bnapply(float* __restrict__ out) {
    int i = blockIdx.x * blockDim.x + threadIdx.x;
    if (i >= NA * 128) return;
    int c = i & 127;
    out[i] = fmaxf(g_hm[i] * g_bnscale[c] + g_bnshift[c], 0.f);
}

// ----------------- launch -----------------
extern "C" void kernel_launch(void* const* d_in, const int* in_sizes, int n_in,
                              void* d_out, int out_size) {
    const float* atom_feats   = (const float*)d_in[0];
    const float* bond_feats   = (const float*)d_in[1];
    const float* global_feats = (const float*)d_in[2];
    const float* W_atom       = (const float*)d_in[3];
    const float* W_bond       = (const float*)d_in[4];
    const float* W_global     = (const float*)d_in[5];
    const float* attn_l       = (const float*)d_in[6];
    const float* attn_r       = (const float*)d_in[7];
    const float* bn_gamma     = (const float*)d_in[8];
    const float* bn_beta      = (const float*)d_in[9];
    const int*   src          = (const int*)d_in[10];
    const int*   dst          = (const int*)d_in[11];
    const int*   gid          = (const int*)d_in[12];
    float* out = (float*)d_out;

    static bool attr_done = false;
    if (!attr_done) {
        cudaFuncSetAttribute(k_gemm, cudaFuncAttributeMaxDynamicSharedMemorySize,
                             2 * STG_BYTES);
        attr_done = true;
    }

    const int nscan = (NA + 1023) / 1024;   // 98

    k_prep<<<653, 256>>>(W_atom, W_bond, attn_l, attn_r);
    k_glob<<<(NG + 15) / 16, 256>>>(global_feats, W_global, attn_l);
    k_atom<<<NA / 8, 256>>>(atom_feats, gid);
    k_bond<<<NB / 8, 256>>>(bond_feats, src, dst);
    k_scan1<<<nscan, 1024>>>();
    k_scan2<<<1, 32>>>(nscan);
    k_scan3<<<nscan, 1024>>>();
    k_scatter<<<(NB + 255) / 256, 256>>>(dst);
    k_gather<<<NA / 8, 256>>>(atom_feats, bond_feats, src, gid);
    k_gemm<<<(NA + 63) / 64, 256, 2 * STG_BYTES>>>();
    k_bnstats<<<(NA + 511) / 512, 128>>>();
    k_bnfinal<<<1, 128>>>(bn_gamma, bn_beta);
    k_bnapply<<<(NA * 128 + 1023) / 1024, 1024>>>(out);
}

// round 4
// speedup vs baseline: 1.3159x; 1.0733x over previous
#include <cuda_runtime.h>
#include <cuda_bf16.h>

#define NA 100000
#define NB 400000
#define NG 5000
#define SLOPEC 0.2f

// ----------------- device scratch (static; no allocations) -----------------
__device__ __align__(256) __nv_bfloat16 g_Zhi[(size_t)(NA + 64) * 512];
__device__ __align__(256) __nv_bfloat16 g_Zlo[(size_t)(NA + 64) * 512];
__device__ __align__(256) float         g_hm[(size_t)(NA + 64) * 128];
__device__ __align__(256) float         g_U[NG * 256];
__device__ float         g_elu[NG * 2];
__device__ float         g_elh[NA * 2], g_er[NA * 2], g_eu[NA * 2];
__device__ unsigned      g_emaxkey[NA * 2];
__device__ __align__(16) float g_ehee[NB * 4];     // (eh0, eh1, ee0, ee1) in bond order
__device__ __align__(8)  float g_ele[NB * 2];      // bond logits el (bond order)
__device__ int           g_deg[NA], g_cursor[NA];
__device__ __align__(8)  int2   g_bsrc[NB];        // CSR order: (bond, src)
__device__ __align__(16) float4 g_edata[NB];       // CSR order: logits
__device__ int2          g_range[NA];
__device__ int           g_bsum[128], g_boff[128];
__device__ float         g_wAl[256], g_wAr[256], g_wBl[256];
__device__ __align__(256) __nv_bfloat16 g_WhiT[128 * 512];  // [n][k], x0.5 folded
__device__ __align__(256) __nv_bfloat16 g_WloT[128 * 512];
__device__ float         g_bnsum[128], g_bnsumsq[128], g_bnscale[128], g_bnshift[128];

// ----------------- helpers -----------------
__device__ __forceinline__ float lrelu(float x) { return x >= 0.f ? x : SLOPEC * x; }

__device__ __forceinline__ unsigned fkey(float f) {
    unsigned u = __float_as_uint(f);
    return (u & 0x80000000u) ? ~u : (u | 0x80000000u);
}
__device__ __forceinline__ float funkey(unsigned u) {
    u = (u & 0x80000000u) ? (u & 0x7fffffffu) : ~u;
    return __uint_as_float(u);
}
__device__ __forceinline__ float dot4(float4 a, float4 b) {
    return a.x * b.x + a.y * b.y + a.z * b.z + a.w * b.w;
}
__device__ __forceinline__ float wsum(float v) {
#pragma unroll
    for (int o = 16; o > 0; o >>= 1) v += __shfl_xor_sync(0xffffffffu, v, o);
    return v;
}

__device__ __forceinline__ void split_store(__nv_bfloat16* ph, __nv_bfloat16* pl, float4 v) {
    __nv_bfloat162 h0 = __floats2bfloat162_rn(v.x, v.y);
    __nv_bfloat162 h1 = __floats2bfloat162_rn(v.z, v.w);
    __nv_bfloat162 l0 = __floats2bfloat162_rn(v.x - __bfloat162float(h0.x),
                                              v.y - __bfloat162float(h0.y));
    __nv_bfloat162 l1 = __floats2bfloat162_rn(v.z - __bfloat162float(h1.x),
                                              v.w - __bfloat162float(h1.y));
    *(__nv_bfloat162*)(ph)     = h0;
    *(__nv_bfloat162*)(ph + 2) = h1;
    *(__nv_bfloat162*)(pl)     = l0;
    *(__nv_bfloat162*)(pl + 2) = l1;
}

// ----------------- merged prep: zero + fold probes + split/transpose weights ------
__global__ void k_prep(const float* __restrict__ Wa, const float* __restrict__ Wb,
                       const float* __restrict__ al, const float* __restrict__ ar) {
    int b = blockIdx.x, t = threadIdx.x;
    if (b < 391) {
        int i = b * 256 + t;
        if (i < NA) g_deg[i] = 0;
        if (b == 0 && t < 128) { g_bnsum[t] = 0.f; g_bnsumsq[t] = 0.f; }
    } else if (b < 397) {
        if (t < 128) {
            int m = (b - 391) >> 1, h = (b - 391) & 1;
            const float* W  = (m == 2) ? Wb : Wa;
            const float* at = (m == 1) ? ar : al;
            float s = 0.f;
            for (int d = 0; d < 128; d++) s += W[t * 256 + h * 128 + d] * at[h * 128 + d];
            float* o = (m == 0) ? g_wAl : (m == 1) ? g_wAr : g_wBl;
            o[h * 128 + t] = s;
        }
    } else {
        int idx = (b - 397) * 256 + t;   // 65536 = n*512 + k
        int n = idx >> 9, k = idx & 511;
        int s2 = k >> 7, i = k & 127, h = s2 & 1;
        const float* W = (s2 < 2) ? Wa : Wb;
        float x = 0.5f * W[i * 256 + h * 128 + n];
        __nv_bfloat16 hi = __float2bfloat16(x);
        g_WhiT[idx] = hi;
        g_WloT[idx] = __float2bfloat16(x - __bfloat162float(hi));
    }
}

// ----------------- per-global projection + logit; 16 globals per block ----------
__global__ __launch_bounds__(256) void k_glob(const float* __restrict__ gf,
                                              const float* __restrict__ Wg,
                                              const float* __restrict__ al) {
    __shared__ float s_gf[16][128];
    __shared__ float s_elu[32];
    int g0 = blockIdx.x * 16, t = threadIdx.x, lane = t & 31;
    int head = t >> 7;
    if (t < 32) s_elu[t] = 0.f;
#pragma unroll
    for (int p = 0; p < 8; p++) {
        int e = t + p * 256;
        int j = e >> 7, d = e & 127;
        s_gf[j][d] = (g0 + j < NG) ? gf[(g0 + j) * 128 + d] : 0.f;
    }
    __syncthreads();
    float acc[16];
#pragma unroll
    for (int j = 0; j < 16; j++) acc[j] = 0.f;
    for (int i = 0; i < 128; i++) {
        float w = Wg[i * 256 + t];
#pragma unroll
        for (int j = 0; j < 16; j++) acc[j] += s_gf[j][i] * w;
    }
    float alt = al[t];
#pragma unroll
    for (int j = 0; j < 16; j++) {
        if (g0 + j < NG) g_U[(g0 + j) * 256 + t] = acc[j];
        float p = wsum(acc[j] * alt);
        if (lane == 0) atomicAdd(&s_elu[j * 2 + head], p);
    }
    __syncthreads();
    if (t < 32) {
        int j = t >> 1, h = t & 1;
        if (g0 + j < NG) g_elu[(g0 + j) * 2 + h] = s_elu[j * 2 + h];
    }
}

// ----------------- atom: streaming dot only -----------------
__global__ void k_atom_dot(const float* __restrict__ af) {
    __shared__ float s_l[256], s_r[256];
    int t = threadIdx.x, lane = t & 31;
    if (t < 256) { s_l[t] = g_wAl[t]; s_r[t] = g_wAr[t]; }
    __syncthreads();
    int a = blockIdx.x * 8 + (t >> 5);
    float4 v = *(const float4*)&af[(size_t)a * 128 + lane * 4];
    float al0 = wsum(dot4(v, *(const float4*)&s_l[lane * 4]));
    float al1 = wsum(dot4(v, *(const float4*)&s_l[128 + lane * 4]));
    float ar0 = wsum(dot4(v, *(const float4*)&s_r[lane * 4]));
    float ar1 = wsum(dot4(v, *(const float4*)&s_r[128 + lane * 4]));
    if (lane == 0) {
        *(float2*)&g_elh[2 * a] = make_float2(al0, al1);
        *(float2*)&g_er[2 * a]  = make_float2(ar0, ar1);
    }
}

// ----------------- atom epilogue: thread-per-atom (parallel scattered loads) ----
__global__ void k_atom_epi(const int* __restrict__ gid) {
    int a = blockIdx.x * blockDim.x + threadIdx.x;
    if (a >= NA) return;
    float2 er = *(const float2*)&g_er[2 * a];
    int g = gid[a];
    float2 lu = *(const float2*)&g_elu[2 * g];
    float eu0 = lrelu(lu.x + er.x);
    float eu1 = lrelu(lu.y + er.y);
    *(float2*)&g_eu[2 * a] = make_float2(eu0, eu1);
    *(uint2*)&g_emaxkey[2 * a] = make_uint2(fkey(eu0), fkey(eu1));
}

// ----------------- bond: streaming dot only -----------------
__global__ void k_bond_dot(const float* __restrict__ bf) {
    __shared__ float s_l[256];
    int t = threadIdx.x, lane = t & 31;
    if (t < 256) s_l[t] = g_wBl[t];
    __syncthreads();
    int b = blockIdx.x * 8 + (t >> 5);
    float4 v = *(const float4*)&bf[(size_t)b * 128 + lane * 4];
    float el0 = wsum(dot4(v, *(const float4*)&s_l[lane * 4]));
    float el1 = wsum(dot4(v, *(const float4*)&s_l[128 + lane * 4]));
    if (lane == 0) *(float2*)&g_ele[2 * b] = make_float2(el0, el1);
}

// ----------------- bond epilogue: thread-per-bond ----------------------------
__global__ void k_bond_epi(const int* __restrict__ src, const int* __restrict__ dst) {
    int b = blockIdx.x * blockDim.x + threadIdx.x;
    if (b >= NB) return;
    int s = src[b], d = dst[b];
    float2 el = *(const float2*)&g_ele[2 * b];
    float2 lh = *(const float2*)&g_elh[2 * s];
    float2 er = *(const float2*)&g_er[2 * d];
    float eh0 = lrelu(lh.x + er.x);
    float eh1 = lrelu(lh.y + er.y);
    float ee0 = lrelu(el.x + er.x);
    float ee1 = lrelu(el.y + er.y);
    *(float4*)&g_ehee[4 * b] = make_float4(eh0, eh1, ee0, ee1);
    atomicMax(&g_emaxkey[2 * d],     fkey(fmaxf(eh0, ee0)));
    atomicMax(&g_emaxkey[2 * d + 1], fkey(fmaxf(eh1, ee1)));
    atomicAdd(&g_deg[d], 1);
}

// ---- 2-level exclusive scan of degrees -> CSR ranges ----
__global__ void k_scan1() {
    __shared__ int s[1024];
    int t = threadIdx.x, idx = blockIdx.x * 1024 + t;
    s[t] = (idx < NA) ? g_deg[idx] : 0;
    __syncthreads();
    for (int o = 512; o > 0; o >>= 1) {
        if (t < o) s[t] += s[t + o];
        __syncthreads();
    }
    if (t == 0) g_bsum[blockIdx.x] = s[0];
}
__global__ void k_scan2(int nblk) {
    if (threadIdx.x == 0) {
        int run = 0;
        for (int i = 0; i < nblk; i++) { int v = g_bsum[i]; g_boff[i] = run; run += v; }
    }
}
__global__ void k_scan3() {
    __shared__ int s[1024];
    int t = threadIdx.x, idx = blockIdx.x * 1024 + t;
    int v = (idx < NA) ? g_deg[idx] : 0;
    s[t] = v;
    __syncthreads();
    for (int o = 1; o < 1024; o <<= 1) {
        int add = (t >= o) ? s[t - o] : 0;
        __syncthreads();
        s[t] += add;
        __syncthreads();
    }
    int excl = s[t] - v + g_boff[blockIdx.x];
    if (idx < NA) { g_range[idx] = make_int2(excl, excl + v); g_cursor[idx] = excl; }
}

// scatter bonds into CSR order; carry src + logits along to kill indirection
__global__ void k_scatter(const int* __restrict__ src, const int* __restrict__ dst) {
    int b = blockIdx.x * blockDim.x + threadIdx.x;
    if (b >= NB) return;
    int pos = atomicAdd(&g_cursor[dst[b]], 1);
    g_bsrc[pos] = make_int2(b, src[b]);
    g_edata[pos] = *(const float4*)&g_ehee[4 * b];
}

// ---- gather: softmax-weighted raw-feature aggregation ----
__global__ __launch_bounds__(256) void k_gather(const float* __restrict__ af,
                                                const float* __restrict__ bf,
                                                const int* __restrict__ gid) {
    int lane = threadIdx.x & 31;
    int a = blockIdx.x * 8 + (threadIdx.x >> 5);
    uint2 mk = *(const uint2*)&g_emaxkey[2 * a];
    float emax0 = funkey(mk.x), emax1 = funkey(mk.y);
    int2 rg = g_range[a];
    float4 aH0 = make_float4(0, 0, 0, 0), aH1 = aH0, aE0 = aH0, aE1 = aH0;
    float s0 = 0.f, s1 = 0.f;
    int i = rg.x, end = rg.y;
    for (; i + 4 <= end; i += 4) {
        int2 bs[4];
        float4 ev[4], avs[4], bvs[4];
#pragma unroll
        for (int j = 0; j < 4; j++) bs[j] = g_bsrc[i + j];
#pragma unroll
        for (int j = 0; j < 4; j++) ev[j] = g_edata[i + j];
#pragma unroll
        for (int j = 0; j < 4; j++) {
            avs[j] = *(const float4*)&af[(size_t)bs[j].y * 128 + lane * 4];
            bvs[j] = *(const float4*)&bf[(size_t)bs[j].x * 128 + lane * 4];
        }
#pragma unroll
        for (int j = 0; j < 4; j++) {
            float xh0 = __expf(ev[j].x - emax0), xh1 = __expf(ev[j].y - emax1);
            float xe0 = __expf(ev[j].z - emax0), xe1 = __expf(ev[j].w - emax1);
            s0 += xh0 + xe0; s1 += xh1 + xe1;
            aH0.x += xh0 * avs[j].x; aH0.y += xh0 * avs[j].y;
            aH0.z += xh0 * avs[j].z; aH0.w += xh0 * avs[j].w;
            aH1.x += xh1 * avs[j].x; aH1.y += xh1 * avs[j].y;
            aH1.z += xh1 * avs[j].z; aH1.w += xh1 * avs[j].w;
            aE0.x += xe0 * bvs[j].x; aE0.y += xe0 * bvs[j].y;
            aE0.z += xe0 * bvs[j].z; aE0.w += xe0 * bvs[j].w;
            aE1.x += xe1 * bvs[j].x; aE1.y += xe1 * bvs[j].y;
            aE1.z += xe1 * bvs[j].z; aE1.w += xe1 * bvs[j].w;
        }
    }
    for (; i < end; i++) {
        int2 bsx = g_bsrc[i];
        float4 ev = g_edata[i];
        float4 av = *(const float4*)&af[(size_t)bsx.y * 128 + lane * 4];
        float4 bv = *(const float4*)&bf[(size_t)bsx.x * 128 + lane * 4];
        float xh0 = __expf(ev.x - emax0), xh1 = __expf(ev.y - emax1);
        float xe0 = __expf(ev.z - emax0), xe1 = __expf(ev.w - emax1);
        s0 += xh0 + xe0; s1 += xh1 + xe1;
        aH0.x += xh0 * av.x; aH0.y += xh0 * av.y; aH0.z += xh0 * av.z; aH0.w += xh0 * av.w;
        aH1.x += xh1 * av.x; aH1.y += xh1 * av.y; aH1.z += xh1 * av.z; aH1.w += xh1 * av.w;
        aE0.x += xe0 * bv.x; aE0.y += xe0 * bv.y; aE0.z += xe0 * bv.z; aE0.w += xe0 * bv.w;
        aE1.x += xe1 * bv.x; aE1.y += xe1 * bv.y; aE1.z += xe1 * bv.z; aE1.w += xe1 * bv.w;
    }
    float2 euv = *(const float2*)&g_eu[2 * a];
    float xu0 = __expf(euv.x - emax0);
    float xu1 = __expf(euv.y - emax1);
    float inv0 = 1.f / (s0 + xu0);
    float inv1 = 1.f / (s1 + xu1);
    size_t zb = (size_t)a * 512 + lane * 4;
    split_store(&g_Zhi[zb], &g_Zlo[zb],
                make_float4(aH0.x * inv0, aH0.y * inv0, aH0.z * inv0, aH0.w * inv0));
    split_store(&g_Zhi[zb + 128], &g_Zlo[zb + 128],
                make_float4(aH1.x * inv1, aH1.y * inv1, aH1.z * inv1, aH1.w * inv1));
    split_store(&g_Zhi[zb + 256], &g_Zlo[zb + 256],
                make_float4(aE0.x * inv0, aE0.y * inv0, aE0.z * inv0, aE0.w * inv0));
    split_store(&g_Zhi[zb + 384], &g_Zlo[zb + 384],
                make_float4(aE1.x * inv1, aE1.y * inv1, aE1.z * inv1, aE1.w * inv1));
    int g = gid[a];
    float4 u0 = *(const float4*)&g_U[g * 256 + lane * 4];
    float4 u1 = *(const float4*)&g_U[g * 256 + 128 + lane * 4];
    float au0 = 0.5f * xu0 * inv0, au1 = 0.5f * xu1 * inv1;
    float4 hb = make_float4(u0.x * au0 + u1.x * au1, u0.y * au0 + u1.y * au1,
                            u0.z * au0 + u1.z * au1, u0.w * au0 + u1.w * au1);
    *(float4*)&g_hm[(size_t)a * 128 + lane * 4] = hb;
}

// ---- split-bf16 tensor-core GEMM with cp.async double buffering + fused bnstats ----
#define STG_BYTES 55296
#define CP16(saddr, gptr) \
    asm volatile("cp.async.cg.shared.global [%0], [%1], 16;\n" :: "r"(saddr), "l"(gptr))

__device__ __forceinline__ void gemm_load_stage(unsigned char* dsm, int st, int row0,
                                                int k0, int tid) {
    unsigned sa = (unsigned)__cvta_generic_to_shared(dsm + st * STG_BYTES);
#pragma unroll
    for (int p = 0; p < 2; p++) {
        int e = tid + p * 256;
        int r = e >> 3, seg = e & 7;
        size_t go = (size_t)(row0 + r) * 512 + k0 + seg * 8;
        unsigned so = (unsigned)(r * 72 + seg * 8) * 2;
        CP16(sa + so, &g_Zhi[go]);
        CP16(sa + 9216 + so, &g_Zlo[go]);
    }
#pragma unroll
    for (int p = 0; p < 4; p++) {
        int e = tid + p * 256;
        int n = e >> 3, seg = e & 7;
        size_t go = (size_t)n * 512 + k0 + seg * 8;
        unsigned so = (unsigned)(n * 72 + seg * 8) * 2;
        CP16(sa + 18432 + so, &g_WhiT[go]);
        CP16(sa + 36864 + so, &g_WloT[go]);
    }
    asm volatile("cp.async.commit_group;\n" ::);
}

#define MMA_OP(c, A0, A1, A2, A3, B0, B1)                                              \
    asm volatile("mma.sync.aligned.m16n8k16.row.col.f32.bf16.bf16.f32 "                \
                 "{%0,%1,%2,%3}, {%4,%5,%6,%7}, {%8,%9}, {%0,%1,%2,%3};"               \
                 : "+f"(c[0]), "+f"(c[1]), "+f"(c[2]), "+f"(c[3])                      \
                 : "r"(A0), "r"(A1), "r"(A2), "r"(A3), "r"(B0), "r"(B1))

__global__ __launch_bounds__(256) void k_gemm() {
    extern __shared__ __align__(16) unsigned char dsm[];
    __shared__ float s_sum[128], s_ssq[128];
    int tid = threadIdx.x;
    if (tid < 128) { s_sum[tid] = 0.f; s_ssq[tid] = 0.f; }
    int row0 = blockIdx.x * 64;
    int wid = tid >> 5, lane = tid & 31;
    int wm = wid & 3, wn = wid >> 2;
    int g = lane >> 2, t = lane & 3;
    float acc[8][4];
#pragma unroll
    for (int i = 0; i < 8; i++)
#pragma unroll
        for (int j = 0; j < 4; j++) acc[i][j] = 0.f;

    gemm_load_stage(dsm, 0, row0, 0, tid);
#pragma unroll 1
    for (int c = 0; c < 8; c++) {
        if (c < 7) {
            gemm_load_stage(dsm, (c + 1) & 1, row0, (c + 1) * 64, tid);
            asm volatile("cp.async.wait_group 1;\n" ::);
        } else {
            asm volatile("cp.async.wait_group 0;\n" ::);
        }
        __syncthreads();
        const __nv_bfloat16* sAh = (const __nv_bfloat16*)(dsm + (c & 1) * STG_BYTES);
        const __nv_bfloat16* sAl = sAh + 4608;
        const __nv_bfloat16* sBh = sAh + 9216;
        const __nv_bfloat16* sBl = sAh + 18432;
        int m0 = wm * 16;
#pragma unroll
        for (int s = 0; s < 4; s++) {
            int ka = s * 16 + 2 * t;
            unsigned ah0 = *(const unsigned*)&sAh[(m0 + g) * 72 + ka];
            unsigned ah1 = *(const unsigned*)&sAh[(m0 + g + 8) * 72 + ka];
            unsigned ah2 = *(const unsigned*)&sAh[(m0 + g) * 72 + ka + 8];
            unsigned ah3 = *(const unsigned*)&sAh[(m0 + g + 8) * 72 + ka + 8];
            unsigned al0 = *(const unsigned*)&sAl[(m0 + g) * 72 + ka];
            unsigned al1 = *(const unsigned*)&sAl[(m0 + g + 8) * 72 + ka];
            unsigned al2 = *(const unsigned*)&sAl[(m0 + g) * 72 + ka + 8];
            unsigned al3 = *(const unsigned*)&sAl[(m0 + g + 8) * 72 + ka + 8];
#pragma unroll
            for (int nt = 0; nt < 8; nt++) {
                int n = wn * 64 + nt * 8 + g;
                unsigned bh0 = *(const unsigned*)&sBh[n * 72 + ka];
                unsigned bh1 = *(const unsigned*)&sBh[n * 72 + ka + 8];
                unsigned bl0 = *(const unsigned*)&sBl[n * 72 + ka];
                unsigned bl1 = *(const unsigned*)&sBl[n * 72 + ka + 8];
                MMA_OP(acc[nt], ah0, ah1, ah2, ah3, bh0, bh1);
                MMA_OP(acc[nt], al0, al1, al2, al3, bh0, bh1);
                MMA_OP(acc[nt], ah0, ah1, ah2, ah3, bl0, bl1);
            }
        }
        __syncthreads();
    }
    // epilogue: add base (global-edge contribution), store hm, fused bn col-sums
#pragma unroll
    for (int nt = 0; nt < 8; nt++) {
        int col = wn * 64 + nt * 8 + 2 * t;
        int r0 = row0 + wm * 16 + g;
        int r1 = r0 + 8;
        float sx = 0.f, sy = 0.f, qx = 0.f, qy = 0.f;
        if (r0 < NA) {
            float2 b = *(float2*)&g_hm[(size_t)r0 * 128 + col];
            float vx = b.x + acc[nt][0], vy = b.y + acc[nt][1];
            *(float2*)&g_hm[(size_t)r0 * 128 + col] = make_float2(vx, vy);
            sx += vx; sy += vy; qx += vx * vx; qy += vy * vy;
        }
        if (r1 < NA) {
            float2 b = *(float2*)&g_hm[(size_t)r1 * 128 + col];
            float vx = b.x + acc[nt][2], vy = b.y + acc[nt][3];
            *(float2*)&g_hm[(size_t)r1 * 128 + col] = make_float2(vx, vy);
            sx += vx; sy += vy; qx += vx * vx; qy += vy * vy;
        }
#pragma unroll
        for (int o = 4; o <= 16; o <<= 1) {       // reduce over g (lane bits 2..4)
            sx += __shfl_xor_sync(0xffffffffu, sx, o);
            sy += __shfl_xor_sync(0xffffffffu, sy, o);
            qx += __shfl_xor_sync(0xffffffffu, qx, o);
            qy += __shfl_xor_sync(0xffffffffu, qy, o);
        }
        if (g == 0) {
            atomicAdd(&s_sum[col], sx);
            atomicAdd(&s_sum[col + 1], sy);
            atomicAdd(&s_ssq[col], qx);
            atomicAdd(&s_ssq[col + 1], qy);
        }
    }
    __syncthreads();
    if (tid < 128) {
        atomicAdd(&g_bnsum[tid], s_sum[tid]);
        atomicAdd(&g_bnsumsq[tid], s_ssq[tid]);
    }
}

// ---- batchnorm finalize + apply ----
__global__ void k_bnfinal(const float* __restrict__ gamma, const float* __restrict__ beta) {
    int t = threadIdx.x;
    float m = g_bnsum[t] / (float)NA;
    float var = g_bnsumsq[t] / (float)NA - m * m;
    float sc = gamma[t] / sqrtf(var + 1e-5f);
    g_bnscale[t] = sc;
    g_bnshift[t] = beta[t] - m * sc;
}
__global__ void k_bnapply(float* __restrict__ out) {
    int i = blockIdx.x * blockDim.x + threadIdx.x;
    if (i >= NA * 128) return;
    int c = i & 127;
    out[i] = fmaxf(g_hm[i] * g_bnscale[c] + g_bnshift[c], 0.f);
}

// ----------------- launch -----------------
extern "C" void kernel_launch(void* const* d_in, const int* in_sizes, int n_in,
                              void* d_out, int out_size) {
    const float* atom_feats   = (const float*)d_in[0];
    const float* bond_feats   = (const float*)d_in[1];
    const float* global_feats = (const float*)d_in[2];
    const float* W_atom       = (const float*)d_in[3];
    const float* W_bond       = (const float*)d_in[4];
    const float* W_global     = (const float*)d_in[5];
    const float* attn_l       = (const float*)d_in[6];
    const float* attn_r       = (const float*)d_in[7];
    const float* bn_gamma     = (const float*)d_in[8];
    const float* bn_beta      = (const float*)d_in[9];
    const int*   src          = (const int*)d_in[10];
    const int*   dst          = (const int*)d_in[11];
    const int*   gid          = (const int*)d_in[12];
    float* out = (float*)d_out;

    cudaFuncSetAttribute(k_gemm, cudaFuncAttributeMaxDynamicSharedMemorySize,
                         2 * STG_BYTES);

    const int nscan = (NA + 1023) / 1024;   // 98

    k_prep<<<653, 256>>>(W_atom, W_bond, attn_l, attn_r);
    k_glob<<<(NG + 15) / 16, 256>>>(global_feats, W_global, attn_l);
    k_atom_dot<<<NA / 8, 256>>>(atom_feats);
    k_atom_epi<<<(NA + 255) / 256, 256>>>(gid);
    k_bond_dot<<<NB / 8, 256>>>(bond_feats);
    k_bond_epi<<<(NB + 255) / 256, 256>>>(src, dst);
    k_scan1<<<nscan, 1024>>>();
    k_scan2<<<1, 32>>>(nscan);
    k_scan3<<<nscan, 1024>>>();
    k_scatter<<<(NB + 255) / 256, 256>>>(src, dst);
    k_gather<<<NA / 8, 256>>>(atom_feats, bond_feats, gid);
    k_gemm<<<(NA + 63) / 64, 256, 2 * STG_BYTES>>>();
    k_bnfinal<<<1, 128>>>(bn_gamma, bn_beta);
    k_bnapply<<<(NA * 128 + 1023) / 1024, 1024>>>(out);
}